// round 15
// baseline (speedup 1.0000x reference)
#include <cuda_runtime.h>
#include <cuda_bf16.h>
#include <cstdint>
#include <cstddef>

#define NSEQ   4096
#define BATCH  4
#define DIMSZ  1024
#define NHEAD  16
#define KLR    64
#define DH     64
#define MROWS  (NSEQ*BATCH)     /* 16384 */
#define QKVDIM (3*DIMSZ)        /* 3072  */

// ---------------- scratch (static device globals; no allocation) -------------
__device__ float g_sef[2 * KLR];                           // col sums of E, F
__device__ float g_xefp[(size_t)4 * 128 * 4096];           // xef split-K partials
__device__ __nv_bfloat16 g_xh [(size_t)MROWS * DIMSZ];     // x split [n][(b,d)]
__device__ __nv_bfloat16 g_xl [(size_t)MROWS * DIMSZ];
__device__ __nv_bfloat16 g_xth[(size_t)MROWS * DIMSZ];     // x^T [(b,d)][n]
__device__ __nv_bfloat16 g_xtl[(size_t)MROWS * DIMSZ];
__device__ __nv_bfloat16 g_efh[128 * NSEQ];                // [E^T;F^T] stacked
__device__ __nv_bfloat16 g_efl[128 * NSEQ];
__device__ __nv_bfloat16 g_xeh[(size_t)BATCH * KLR * DIMSZ];
__device__ __nv_bfloat16 g_xel[(size_t)BATCH * KLR * DIMSZ];
__device__ __nv_bfloat16 g_xfh[(size_t)BATCH * KLR * DIMSZ];
__device__ __nv_bfloat16 g_xfl[(size_t)BATCH * KLR * DIMSZ];
__device__ __nv_bfloat16 g_wqh[(size_t)QKVDIM * DIMSZ];    // W_qkv^T split
__device__ __nv_bfloat16 g_wql[(size_t)QKVDIM * DIMSZ];
__device__ __nv_bfloat16 g_woh[(size_t)DIMSZ * DIMSZ];     // W_out^T split
__device__ __nv_bfloat16 g_wol[(size_t)DIMSZ * DIMSZ];
__device__ __nv_bfloat16 g_qh [(size_t)MROWS * DIMSZ];     // Q split [(n,b)][d]
__device__ __nv_bfloat16 g_ql [(size_t)MROWS * DIMSZ];
__device__ __nv_bfloat16 g_kph[(size_t)BATCH * KLR * DIMSZ]; // Kp [b*64+kl][h*64+d]
__device__ __nv_bfloat16 g_kpl[(size_t)BATCH * KLR * DIMSZ];
__device__ __nv_bfloat16 g_vth[(size_t)BATCH * NHEAD * DH * KLR]; // V^T [bh][d][k]
__device__ __nv_bfloat16 g_vtl[(size_t)BATCH * NHEAD * DH * KLR];
__device__ __nv_bfloat16 g_aoh[(size_t)MROWS * DIMSZ];     // attn out split
__device__ __nv_bfloat16 g_aol[(size_t)MROWS * DIMSZ];

// ============================ small helpers ==================================
__device__ __forceinline__ uint32_t smem_u32(const void* p) {
    uint32_t a;
    asm("{ .reg .u64 t; cvta.to.shared.u64 t, %1; cvt.u32.u64 %0, t; }"
        : "=r"(a) : "l"(p));
    return a;
}
__device__ __forceinline__ uint32_t sw128(uint32_t off) {
    return off ^ ((off >> 3) & 0x70);
}
__device__ __forceinline__ void cp16(uint32_t dst, const void* src) {
    asm volatile("cp.async.cg.shared.global [%0], [%1], 16;"
                 :: "r"(dst), "l"(src));
}
__device__ __forceinline__ void ldsm4(uint32_t* r, uint32_t addr) {
    asm volatile("ldmatrix.sync.aligned.m8n8.x4.shared.b16 {%0,%1,%2,%3}, [%4];"
                 : "=r"(r[0]), "=r"(r[1]), "=r"(r[2]), "=r"(r[3]) : "r"(addr));
}
__device__ __forceinline__ void mma16816(float* c, const uint32_t* a,
                                         uint32_t b0, uint32_t b1) {
    asm volatile(
        "mma.sync.aligned.m16n8k16.row.col.f32.bf16.bf16.f32 "
        "{%0,%1,%2,%3}, {%4,%5,%6,%7}, {%8,%9}, {%0,%1,%2,%3};"
        : "+f"(c[0]), "+f"(c[1]), "+f"(c[2]), "+f"(c[3])
        : "r"(a[0]), "r"(a[1]), "r"(a[2]), "r"(a[3]), "r"(b0), "r"(b1));
}
__device__ __forceinline__ uint32_t pack_bf16_pair(float x, float y,
                                                   uint32_t& lo_out) {
    __nv_bfloat16 hx = __float2bfloat16(x);
    __nv_bfloat16 hy = __float2bfloat16(y);
    __nv_bfloat16 lx = __float2bfloat16(x - __bfloat162float(hx));
    __nv_bfloat16 ly = __float2bfloat16(y - __bfloat162float(hy));
    lo_out = (uint32_t)__bfloat16_as_ushort(lx) |
             ((uint32_t)__bfloat16_as_ushort(ly) << 16);
    return (uint32_t)__bfloat16_as_ushort(hx) |
           ((uint32_t)__bfloat16_as_ushort(hy) << 16);
}
__device__ __forceinline__ void store_split2(__nv_bfloat16* oh, __nv_bfloat16* ol,
                                             size_t idx, float v0, float v1) {
    uint32_t lo, hi = pack_bf16_pair(v0, v1, lo);
    *(uint32_t*)(oh + idx) = hi;
    *(uint32_t*)(ol + idx) = lo;
}

// ========== HMMA GEMM body: C = A(MxK)@B^T(NxK); fp32-split bf16 =============
// MODE 0: fp32 C = acc + bias[col]
// MODE 1: KV: v = acc + rs[row&63]*bias[col]; which==0 -> kph/kpl row-major,
//         which==1 -> vth/vtl transposed per-head [bh][d][k]
// MODE 2: Q: v = acc + bias[col]; split -> Oh/Ol row-major
// MODE 4: plain fp32 C = acc (split-K partials)
#define STAGES      3
#define STAGE_BYTES 65536
#define GEMM_SMEM   (STAGES * STAGE_BYTES)

template <int MODE>
__device__ __forceinline__ void gemm_body(
    const __nv_bfloat16* __restrict__ Ah, const __nv_bfloat16* __restrict__ Al,
    const __nv_bfloat16* __restrict__ Bh, const __nv_bfloat16* __restrict__ Bl,
    const float* __restrict__ bias, const float* __restrict__ rs,
    float* __restrict__ Cf, __nv_bfloat16* __restrict__ Oh,
    __nv_bfloat16* __restrict__ Ol, int N, int Kstride, int kbeg, int kcnt,
    int bm0, int bn0, int which)
{
    extern __shared__ __align__(1024) char smem[];
    const uint32_t sb  = smem_u32(smem);
    const int tid  = threadIdx.x;
    const int lane = tid & 31;
    const int wid  = tid >> 5;
    const int wm   = wid >> 1;
    const int wn   = wid & 1;
    const int niter = kcnt / 64;

    float acc[2][8][4] = {};

    auto load_stage = [&](int stage, int it) {
        const uint32_t base = sb + stage * STAGE_BYTES;
        const int k0 = kbeg + it * 64;
        #pragma unroll
        for (int u = 0; u < 16; u++) {
            int idx  = u * 256 + tid;
            int comp = u >> 2;
            int rem  = idx & 1023;
            int r    = rem >> 3;
            int j    = rem & 7;
            const __nv_bfloat16* p =
                comp == 0 ? Ah : comp == 1 ? Al : comp == 2 ? Bh : Bl;
            int rb = (comp < 2) ? bm0 : bn0;
            uint32_t dst = base + comp * 16384 + sw128((uint32_t)(r * 128 + j * 16));
            cp16(dst, p + (size_t)(rb + r) * Kstride + k0 + j * 8);
        }
    };

    load_stage(0, 0);
    asm volatile("cp.async.commit_group;" ::: "memory");
    if (niter > 1) load_stage(1, 1);
    asm volatile("cp.async.commit_group;" ::: "memory");

    for (int it = 0; it < niter; it++) {
        asm volatile("cp.async.wait_group 1;" ::: "memory");
        __syncthreads();

        int nx = it + 2;
        if (nx < niter) load_stage(nx % STAGES, nx);
        asm volatile("cp.async.commit_group;" ::: "memory");

        const uint32_t st  = sb + (it % STAGES) * STAGE_BYTES;
        const uint32_t sAh = st, sAl = st + 16384, sBh = st + 32768, sBl = st + 49152;

        #pragma unroll
        for (int ks = 0; ks < 4; ks++) {
            uint32_t aH[2][4], aL[2][4], bH[4][4], bL[4][4];
            #pragma unroll
            for (int mi = 0; mi < 2; mi++) {
                int row = wm * 32 + mi * 16 + (lane & 15);
                int col = ks * 32 + ((lane & 16) ? 16 : 0);
                uint32_t off = sw128((uint32_t)(row * 128 + col));
                ldsm4(aH[mi], sAh + off);
                ldsm4(aL[mi], sAl + off);
            }
            #pragma unroll
            for (int ntp = 0; ntp < 4; ntp++) {
                int row = wn * 64 + ntp * 16 + (lane & 7) + ((lane & 16) ? 8 : 0);
                int col = ks * 32 + ((lane & 8) ? 16 : 0);
                uint32_t off = sw128((uint32_t)(row * 128 + col));
                ldsm4(bH[ntp], sBh + off);
                ldsm4(bL[ntp], sBl + off);
            }
            #pragma unroll
            for (int mi = 0; mi < 2; mi++) {
                #pragma unroll
                for (int ni = 0; ni < 8; ni++) {
                    uint32_t b0h = bH[ni >> 1][(ni & 1) * 2];
                    uint32_t b1h = bH[ni >> 1][(ni & 1) * 2 + 1];
                    uint32_t b0l = bL[ni >> 1][(ni & 1) * 2];
                    uint32_t b1l = bL[ni >> 1][(ni & 1) * 2 + 1];
                    mma16816(acc[mi][ni], aH[mi], b0h, b1h);
                    mma16816(acc[mi][ni], aH[mi], b0l, b1l);
                    mma16816(acc[mi][ni], aL[mi], b0h, b1h);
                }
            }
        }
    }

    #pragma unroll
    for (int mi = 0; mi < 2; mi++) {
        #pragma unroll
        for (int ni = 0; ni < 8; ni++) {
            int row = bm0 + wm * 32 + mi * 16 + (lane >> 2);
            int col = bn0 + wn * 64 + ni * 8 + (lane & 3) * 2;
            #pragma unroll
            for (int half = 0; half < 2; half++) {
                int r  = row + half * 8;
                float v0 = acc[mi][ni][half * 2 + 0];
                float v1 = acc[mi][ni][half * 2 + 1];
                if (MODE == 0) {
                    float2 o = {v0 + bias[col], v1 + bias[col + 1]};
                    *(float2*)(Cf + (size_t)r * N + col) = o;
                } else if (MODE == 2) {
                    store_split2(Oh, Ol, (size_t)r * N + col,
                                 v0 + bias[col], v1 + bias[col + 1]);
                } else if (MODE == 1) {
                    float s = rs[r & 63];
                    float w0 = v0 + s * bias[col], w1 = v1 + s * bias[col + 1];
                    if (which == 0) {
                        store_split2(Oh, Ol, (size_t)r * N + col, w0, w1);
                    } else {
                        int b2 = r >> 6, kl = r & 63, hh = col >> 6, d = col & 63;
                        size_t i0 = (((size_t)(b2 * 16 + hh) * 64) + d) * 64 + kl;
                        __nv_bfloat16 h0 = __float2bfloat16(w0);
                        __nv_bfloat16 h1 = __float2bfloat16(w1);
                        Oh[i0]      = h0;
                        Ol[i0]      = __float2bfloat16(w0 - __bfloat162float(h0));
                        Oh[i0 + 64] = h1;
                        Ol[i0 + 64] = __float2bfloat16(w1 - __bfloat162float(h1));
                    }
                } else { // MODE 4: split-K partials
                    float2 o = {v0, v1};
                    *(float2*)(Cf + (size_t)r * N + col) = o;
                }
            }
        }
    }
}

__global__ __launch_bounds__(256) void gemm_out(
    const __nv_bfloat16* __restrict__ Ah, const __nv_bfloat16* __restrict__ Al,
    const __nv_bfloat16* __restrict__ Bh, const __nv_bfloat16* __restrict__ Bl,
    const float* __restrict__ bias, float* __restrict__ C, int N, int K)
{
    gemm_body<0>(Ah, Al, Bh, Bl, bias, nullptr, C, nullptr, nullptr, N, K,
                 0, K, blockIdx.y * 128, blockIdx.x * 128, 0);
}
__global__ __launch_bounds__(256) void gemm_q(const float* __restrict__ bqkv)
{
    gemm_body<2>(g_xh, g_xl, g_wqh, g_wql, bqkv, nullptr, nullptr, g_qh, g_ql,
                 DIMSZ, DIMSZ, 0, DIMSZ, blockIdx.y * 128, blockIdx.x * 128, 0);
}
__global__ __launch_bounds__(256) void gemm_kv(const float* __restrict__ bqkv)
{
    const int which = blockIdx.z;
    gemm_body<1>(which ? g_xfh : g_xeh, which ? g_xfl : g_xel,
                 g_wqh + (size_t)(which + 1) * DIMSZ * DIMSZ,
                 g_wql + (size_t)(which + 1) * DIMSZ * DIMSZ,
                 bqkv + (which + 1) * DIMSZ, g_sef + which * KLR, nullptr,
                 which ? g_vth : g_kph, which ? g_vtl : g_kpl,
                 DIMSZ, DIMSZ, 0, DIMSZ,
                 blockIdx.y * 128, blockIdx.x * 128, which);
}
// xef split-K: grid (32 n-tiles, 4 k-chunks); fp32 partials
__global__ __launch_bounds__(256) void gemm_xef_k()
{
    const int chunk = blockIdx.y;
    gemm_body<4>(g_efh, g_efl, g_xth, g_xtl, nullptr, nullptr,
                 g_xefp + (size_t)chunk * 128 * 4096, nullptr, nullptr,
                 MROWS / 4, NSEQ, chunk * 1024, 1024, 0, blockIdx.x * 128, 0);
}

// ============== reduce xef partials + bf16 split-scatter =====================
__global__ __launch_bounds__(256) void reduce_xef()
{
    int t = blockIdx.x * 256 + threadIdx.x;        // 128 rows x 2048 col-pairs
    int row = t >> 11;
    int col = (t & 2047) << 1;
    size_t base = (size_t)row * 4096 + col;
    float v0 = 0.f, v1 = 0.f;
    #pragma unroll
    for (int c = 0; c < 4; c++) {
        float2 p = *(const float2*)(g_xefp + (size_t)c * 128 * 4096 + base);
        v0 += p.x; v1 += p.y;
    }
    int wch = row >> 6, kl = row & 63, b2 = col >> 10, d = col & 1023;
    store_split2(wch ? g_xfh : g_xeh, wch ? g_xfl : g_xel,
                 (size_t)(b2 * 64 + kl) * 1024 + d, v0, v1);
}

// ============== fp32 -> bf16 hi/lo element-wise split ========================
__global__ __launch_bounds__(256) void split_f32(
    const float* __restrict__ in, __nv_bfloat16* __restrict__ oh,
    __nv_bfloat16* __restrict__ ol, int n4)
{
    int i = blockIdx.x * 256 + threadIdx.x;
    if (i >= n4) return;
    float4 v = ((const float4*)in)[i];
    float f[4] = {v.x, v.y, v.z, v.w};
    ushort4 uh, ul;
    unsigned short* ph = &uh.x;
    unsigned short* pl = &ul.x;
    #pragma unroll
    for (int j = 0; j < 4; j++) {
        __nv_bfloat16 h = __float2bfloat16(f[j]);
        __nv_bfloat16 l = __float2bfloat16(f[j] - __bfloat162float(h));
        ph[j] = __bfloat16_as_ushort(h);
        pl[j] = __bfloat16_as_ushort(l);
    }
    ((ushort4*)oh)[i] = uh;
    ((ushort4*)ol)[i] = ul;
}

// ============== W[K][N] -> W^T[N][K] bf16 hi/lo split ========================
__global__ __launch_bounds__(256) void transpose_split(
    const float* __restrict__ W, __nv_bfloat16* __restrict__ th,
    __nv_bfloat16* __restrict__ tl, int K, int N)
{
    __shared__ float t[32][33];
    const int tx = threadIdx.x, ty = threadIdx.y;
    const int n0 = blockIdx.x * 32, k0 = blockIdx.y * 32;
    #pragma unroll
    for (int i = 0; i < 4; i++)
        t[ty + i * 8][tx] = W[(size_t)(k0 + ty + i * 8) * N + n0 + tx];
    __syncthreads();
    #pragma unroll
    for (int i = 0; i < 4; i++) {
        int n = n0 + ty + i * 8, k = k0 + tx;
        float v = t[tx][ty + i * 8];
        __nv_bfloat16 h = __float2bfloat16(v);
        th[(size_t)n * K + k] = h;
        tl[(size_t)n * K + k] = __float2bfloat16(v - __bfloat162float(h));
    }
}

// ============== column sums of E and F: g_sef[which*64+k] ====================
__global__ __launch_bounds__(256) void colsum2(const float* __restrict__ E,
                                               const float* __restrict__ F)
{
    const int which = blockIdx.x >> 6;
    const int k     = blockIdx.x & 63;
    const float* P  = which ? F : E;
    const int tid   = threadIdx.x;
    float s = 0.f;
    for (int n = tid; n < NSEQ; n += 256)
        s += P[(size_t)n * KLR + k];
    __shared__ float red[256];
    red[tid] = s;
    __syncthreads();
    #pragma unroll
    for (int off = 128; off > 0; off >>= 1) {
        if (tid < off) red[tid] += red[tid + off];
        __syncthreads();
    }
    if (tid == 0) g_sef[which * KLR + k] = red[0];
}

// =================== MMA attention: S=QKp^T, softmax, O=PV ===================
#define ATTN_SMEM 65536

__global__ __launch_bounds__(256) void attn_mma()
{
    extern __shared__ __align__(1024) char smem[];
    const uint32_t sb = smem_u32(smem);
    const int tid  = threadIdx.x;
    const int lane = tid & 31;
    const int w    = tid >> 5;
    const int bh   = blockIdx.y;
    const int b    = bh >> 4;
    const int h    = bh & 15;
    const int n0   = blockIdx.x * 128;

    #pragma unroll
    for (int u = 0; u < 8; u++) {           // q tiles (hi then lo)
        int idx = u * 256 + tid;
        int part = idx >> 10, rem = idx & 1023, r = rem >> 3, j = rem & 7;
        const __nv_bfloat16* src =
            (part ? g_ql : g_qh) +
            ((size_t)(n0 + r) * BATCH + b) * DIMSZ + h * 64 + j * 8;
        cp16(sb + part * 16384 + sw128((uint32_t)(r * 128 + j * 16)), src);
    }
    #pragma unroll
    for (int u = 0; u < 4; u++) {           // kp tiles
        int idx = u * 256 + tid;
        int part = idx >> 9, rem = idx & 511, r = rem >> 3, j = rem & 7;
        const __nv_bfloat16* src =
            (part ? g_kpl : g_kph) + (size_t)(b * 64 + r) * DIMSZ + h * 64 + j * 8;
        cp16(sb + 32768 + part * 8192 + sw128((uint32_t)(r * 128 + j * 16)), src);
    }
    #pragma unroll
    for (int u = 0; u < 4; u++) {           // vt tiles
        int idx = u * 256 + tid;
        int part = idx >> 9, rem = idx & 511, r = rem >> 3, j = rem & 7;
        const __nv_bfloat16* src =
            (part ? g_vtl : g_vth) + (size_t)bh * 4096 + r * 64 + j * 8;
        cp16(sb + 49152 + part * 8192 + sw128((uint32_t)(r * 128 + j * 16)), src);
    }
    asm volatile("cp.async.commit_group;" ::: "memory");
    asm volatile("cp.async.wait_group 0;" ::: "memory");
    __syncthreads();

    const uint32_t sQh = sb, sQl = sb + 16384;
    const uint32_t sKh = sb + 32768, sKl = sb + 40960;
    const uint32_t sVh = sb + 49152, sVl = sb + 57344;

    float acc[8][4] = {};
    #pragma unroll
    for (int ks = 0; ks < 4; ks++) {
        uint32_t aH[4], aL[4], bH[4][4], bL[4][4];
        {
            int row = w * 16 + (lane & 15);
            int col = ks * 32 + ((lane & 16) ? 16 : 0);
            uint32_t off = sw128((uint32_t)(row * 128 + col));
            ldsm4(aH, sQh + off);
            ldsm4(aL, sQl + off);
        }
        #pragma unroll
        for (int ntp = 0; ntp < 4; ntp++) {
            int row = ntp * 16 + (lane & 7) + ((lane & 16) ? 8 : 0);
            int col = ks * 32 + ((lane & 8) ? 16 : 0);
            uint32_t off = sw128((uint32_t)(row * 128 + col));
            ldsm4(bH[ntp], sKh + off);
            ldsm4(bL[ntp], sKl + off);
        }
        #pragma unroll
        for (int ni = 0; ni < 8; ni++) {
            uint32_t b0h = bH[ni >> 1][(ni & 1) * 2];
            uint32_t b1h = bH[ni >> 1][(ni & 1) * 2 + 1];
            uint32_t b0l = bL[ni >> 1][(ni & 1) * 2];
            uint32_t b1l = bL[ni >> 1][(ni & 1) * 2 + 1];
            mma16816(acc[ni], aH, b0h, b1h);
            mma16816(acc[ni], aH, b0l, b1l);
            mma16816(acc[ni], aL, b0h, b1h);
        }
    }

    const float scale = 0.125f;
    float m1 = -1e30f, m2 = -1e30f;
    #pragma unroll
    for (int ni = 0; ni < 8; ni++) {
        #pragma unroll
        for (int c = 0; c < 4; c++) acc[ni][c] *= scale;
        m1 = fmaxf(m1, fmaxf(acc[ni][0], acc[ni][1]));
        m2 = fmaxf(m2, fmaxf(acc[ni][2], acc[ni][3]));
    }
    #pragma unroll
    for (int o = 1; o <= 2; o <<= 1) {
        m1 = fmaxf(m1, __shfl_xor_sync(0xffffffffu, m1, o));
        m2 = fmaxf(m2, __shfl_xor_sync(0xffffffffu, m2, o));
    }
    float s1 = 0.f, s2 = 0.f;
    #pragma unroll
    for (int ni = 0; ni < 8; ni++) {
        acc[ni][0] = __expf(acc[ni][0] - m1);
        acc[ni][1] = __expf(acc[ni][1] - m1);
        acc[ni][2] = __expf(acc[ni][2] - m2);
        acc[ni][3] = __expf(acc[ni][3] - m2);
        s1 += acc[ni][0] + acc[ni][1];
        s2 += acc[ni][2] + acc[ni][3];
    }
    #pragma unroll
    for (int o = 1; o <= 2; o <<= 1) {
        s1 += __shfl_xor_sync(0xffffffffu, s1, o);
        s2 += __shfl_xor_sync(0xffffffffu, s2, o);
    }
    float i1 = 1.0f / s1, i2 = 1.0f / s2;
    #pragma unroll
    for (int ni = 0; ni < 8; ni++) {
        acc[ni][0] *= i1; acc[ni][1] *= i1;
        acc[ni][2] *= i2; acc[ni][3] *= i2;
    }

    uint32_t pH[4][4], pL[4][4];
    #pragma unroll
    for (int j = 0; j < 4; j++) {
        pH[j][0] = pack_bf16_pair(acc[2*j][0],   acc[2*j][1],   pL[j][0]);
        pH[j][1] = pack_bf16_pair(acc[2*j][2],   acc[2*j][3],   pL[j][1]);
        pH[j][2] = pack_bf16_pair(acc[2*j+1][0], acc[2*j+1][1], pL[j][2]);
        pH[j][3] = pack_bf16_pair(acc[2*j+1][2], acc[2*j+1][3], pL[j][3]);
    }
    float out[8][4] = {};
    #pragma unroll
    for (int ks = 0; ks < 4; ks++) {
        uint32_t bH[4][4], bL[4][4];
        #pragma unroll
        for (int ntp = 0; ntp < 4; ntp++) {
            int row = ntp * 16 + (lane & 7) + ((lane & 16) ? 8 : 0);
            int col = ks * 32 + ((lane & 8) ? 16 : 0);
            uint32_t off = sw128((uint32_t)(row * 128 + col));
            ldsm4(bH[ntp], sVh + off);
            ldsm4(bL[ntp], sVl + off);
        }
        #pragma unroll
        for (int ni = 0; ni < 8; ni++) {
            uint32_t b0h = bH[ni >> 1][(ni & 1) * 2];
            uint32_t b1h = bH[ni >> 1][(ni & 1) * 2 + 1];
            uint32_t b0l = bL[ni >> 1][(ni & 1) * 2];
            uint32_t b1l = bL[ni >> 1][(ni & 1) * 2 + 1];
            mma16816(out[ni], pH[ks], b0h, b1h);
            mma16816(out[ni], pH[ks], b0l, b1l);
            mma16816(out[ni], pL[ks], b0h, b1h);
        }
    }

    #pragma unroll
    for (int ni = 0; ni < 8; ni++) {
        int r1 = n0 + w * 16 + (lane >> 2);
        int d  = ni * 8 + (lane & 3) * 2;
        size_t i1x = ((size_t)r1 * BATCH + b) * DIMSZ + h * 64 + d;
        store_split2(g_aoh, g_aol, i1x, out[ni][0], out[ni][1]);
        size_t i2x = ((size_t)(r1 + 8) * BATCH + b) * DIMSZ + h * 64 + d;
        store_split2(g_aoh, g_aol, i2x, out[ni][2], out[ni][3]);
    }
}

// ---------------- launch -----------------------------------------------------
extern "C" void kernel_launch(void* const* d_in, const int* in_sizes, int n_in,
                              void* d_out, int out_size)
{
    const float* x    = (const float*)d_in[0];
    const float* E    = (const float*)d_in[1];
    const float* F    = (const float*)d_in[2];
    const float* Wqkv = (const float*)d_in[3];
    const float* bqkv = (const float*)d_in[4];
    const float* Wout = (const float*)d_in[5];
    const float* bout = (const float*)d_in[6];
    float*       out  = (float*)d_out;

    __nv_bfloat16 *xh, *xl, *xth, *xtl, *efh, *efl, *wqh, *wql, *woh, *wol,
                  *aoh, *aol;
    cudaGetSymbolAddress((void**)&xh,  g_xh);
    cudaGetSymbolAddress((void**)&xl,  g_xl);
    cudaGetSymbolAddress((void**)&xth, g_xth);
    cudaGetSymbolAddress((void**)&xtl, g_xtl);
    cudaGetSymbolAddress((void**)&efh, g_efh);
    cudaGetSymbolAddress((void**)&efl, g_efl);
    cudaGetSymbolAddress((void**)&wqh, g_wqh);
    cudaGetSymbolAddress((void**)&wql, g_wql);
    cudaGetSymbolAddress((void**)&woh, g_woh);
    cudaGetSymbolAddress((void**)&wol, g_wol);
    cudaGetSymbolAddress((void**)&aoh, g_aoh);
    cudaGetSymbolAddress((void**)&aol, g_aol);

    cudaFuncSetAttribute(gemm_out, cudaFuncAttributeMaxDynamicSharedMemorySize,
                         GEMM_SMEM);
    cudaFuncSetAttribute(gemm_q, cudaFuncAttributeMaxDynamicSharedMemorySize,
                         GEMM_SMEM);
    cudaFuncSetAttribute(gemm_kv, cudaFuncAttributeMaxDynamicSharedMemorySize,
                         GEMM_SMEM);
    cudaFuncSetAttribute(gemm_xef_k, cudaFuncAttributeMaxDynamicSharedMemorySize,
                         GEMM_SMEM);
    cudaFuncSetAttribute(attn_mma, cudaFuncAttributeMaxDynamicSharedMemorySize,
                         ATTN_SMEM);

    // 0) prep (R8 structure, vectorized)
    split_f32<<<(MROWS * DIMSZ / 4 + 255) / 256, 256>>>(x, xh, xl,
                                                        MROWS * DIMSZ / 4);
    transpose_split<<<dim3(QKVDIM / 32, DIMSZ / 32), dim3(32, 8)>>>(
        Wqkv, wqh, wql, DIMSZ, QKVDIM);
    transpose_split<<<dim3(DIMSZ / 32, DIMSZ / 32), dim3(32, 8)>>>(
        Wout, woh, wol, DIMSZ, DIMSZ);
    transpose_split<<<dim3(MROWS / 4 / 32, NSEQ / 32), dim3(32, 8)>>>(
        x, xth, xtl, NSEQ, MROWS / 4);
    transpose_split<<<dim3(KLR / 32, NSEQ / 32), dim3(32, 8)>>>(
        E, efh, efl, NSEQ, KLR);
    transpose_split<<<dim3(KLR / 32, NSEQ / 32), dim3(32, 8)>>>(
        F, efh + (size_t)KLR * NSEQ, efl + (size_t)KLR * NSEQ, NSEQ, KLR);
    colsum2<<<128, 256>>>(E, F);

    // 1) xe/xf = [E;F]^T @ x   [HMMA, split-K 4 -> 128 CTAs]
    gemm_xef_k<<<dim3(32, 4), 256, GEMM_SMEM>>>();
    reduce_xef<<<1024, 256>>>();

    // 2) Q = x @ Wq + bq  -> qh/ql   [HMMA]
    gemm_q<<<dim3(DIMSZ / 128, MROWS / 128), 256, GEMM_SMEM>>>(bqkv);

    // 3) Kp/Vp (+ colsum*bias) -> kp / vt splits   [HMMA]
    gemm_kv<<<dim3(8, 2, 2), 256, GEMM_SMEM>>>(bqkv);

    // 4) attention  [HMMA]
    attn_mma<<<dim3(NSEQ / 128, BATCH * NHEAD), 256, ATTN_SMEM>>>();

    // 5) out = ao @ Wout + bout   [HMMA, fp32 C]
    gemm_out<<<dim3(DIMSZ / 128, MROWS / 128), 256, GEMM_SMEM>>>(
        aoh, aol, woh, wol, bout, out, DIMSZ, DIMSZ);
}

// round 16
// speedup vs baseline: 1.5364x; 1.5364x over previous
#include <cuda_runtime.h>
#include <cuda_bf16.h>
#include <cstdint>
#include <cstddef>

#define NSEQ   4096
#define BATCH  4
#define DIMSZ  1024
#define NHEAD  16
#define KLR    64
#define DH     64
#define MROWS  (NSEQ*BATCH)     /* 16384 */
#define QKVDIM (3*DIMSZ)        /* 3072  */

// ---------------- scratch (static device globals; no allocation) -------------
__device__ float g_sef[2 * KLR];                           // col sums of E, F
__device__ __nv_bfloat16 g_xh [(size_t)MROWS * DIMSZ];     // x split [n][(b,d)]
__device__ __nv_bfloat16 g_xl [(size_t)MROWS * DIMSZ];
__device__ __nv_bfloat16 g_xth[(size_t)MROWS * DIMSZ];     // x^T [(b,d)][n]
__device__ __nv_bfloat16 g_xtl[(size_t)MROWS * DIMSZ];
__device__ __nv_bfloat16 g_efh[128 * NSEQ];                // [E^T;F^T] stacked
__device__ __nv_bfloat16 g_efl[128 * NSEQ];
__device__ __nv_bfloat16 g_xeh[(size_t)BATCH * KLR * DIMSZ];
__device__ __nv_bfloat16 g_xel[(size_t)BATCH * KLR * DIMSZ];
__device__ __nv_bfloat16 g_xfh[(size_t)BATCH * KLR * DIMSZ];
__device__ __nv_bfloat16 g_xfl[(size_t)BATCH * KLR * DIMSZ];
__device__ __nv_bfloat16 g_wqh[(size_t)QKVDIM * DIMSZ];    // W_qkv^T split
__device__ __nv_bfloat16 g_wql[(size_t)QKVDIM * DIMSZ];
__device__ __nv_bfloat16 g_woh[(size_t)DIMSZ * DIMSZ];     // W_out^T split
__device__ __nv_bfloat16 g_wol[(size_t)DIMSZ * DIMSZ];
__device__ __nv_bfloat16 g_qh [(size_t)MROWS * DIMSZ];     // Q split [(n,b)][d]
__device__ __nv_bfloat16 g_ql [(size_t)MROWS * DIMSZ];
__device__ __nv_bfloat16 g_kph[(size_t)BATCH * KLR * DIMSZ]; // Kp [b*64+kl][h*64+d]
__device__ __nv_bfloat16 g_kpl[(size_t)BATCH * KLR * DIMSZ];
__device__ __nv_bfloat16 g_vth[(size_t)BATCH * NHEAD * DH * KLR]; // V^T [bh][d][k]
__device__ __nv_bfloat16 g_vtl[(size_t)BATCH * NHEAD * DH * KLR];
__device__ __nv_bfloat16 g_aoh[(size_t)MROWS * DIMSZ];     // attn out split
__device__ __nv_bfloat16 g_aol[(size_t)MROWS * DIMSZ];

// ============================ small helpers ==================================
__device__ __forceinline__ uint32_t smem_u32(const void* p) {
    uint32_t a;
    asm("{ .reg .u64 t; cvta.to.shared.u64 t, %1; cvt.u32.u64 %0, t; }"
        : "=r"(a) : "l"(p));
    return a;
}
__device__ __forceinline__ uint32_t sw128(uint32_t off) {
    return off ^ ((off >> 3) & 0x70);
}
__device__ __forceinline__ void cp16(uint32_t dst, const void* src) {
    asm volatile("cp.async.cg.shared.global [%0], [%1], 16;"
                 :: "r"(dst), "l"(src));
}
__device__ __forceinline__ void ldsm4(uint32_t* r, uint32_t addr) {
    asm volatile("ldmatrix.sync.aligned.m8n8.x4.shared.b16 {%0,%1,%2,%3}, [%4];"
                 : "=r"(r[0]), "=r"(r[1]), "=r"(r[2]), "=r"(r[3]) : "r"(addr));
}
__device__ __forceinline__ void mma16816(float* c, const uint32_t* a,
                                         uint32_t b0, uint32_t b1) {
    asm volatile(
        "mma.sync.aligned.m16n8k16.row.col.f32.bf16.bf16.f32 "
        "{%0,%1,%2,%3}, {%4,%5,%6,%7}, {%8,%9}, {%0,%1,%2,%3};"
        : "+f"(c[0]), "+f"(c[1]), "+f"(c[2]), "+f"(c[3])
        : "r"(a[0]), "r"(a[1]), "r"(a[2]), "r"(a[3]), "r"(b0), "r"(b1));
}
__device__ __forceinline__ uint32_t pack_bf16_pair(float x, float y,
                                                   uint32_t& lo_out) {
    __nv_bfloat16 hx = __float2bfloat16(x);
    __nv_bfloat16 hy = __float2bfloat16(y);
    __nv_bfloat16 lx = __float2bfloat16(x - __bfloat162float(hx));
    __nv_bfloat16 ly = __float2bfloat16(y - __bfloat162float(hy));
    lo_out = (uint32_t)__bfloat16_as_ushort(lx) |
             ((uint32_t)__bfloat16_as_ushort(ly) << 16);
    return (uint32_t)__bfloat16_as_ushort(hx) |
           ((uint32_t)__bfloat16_as_ushort(hy) << 16);
}
__device__ __forceinline__ void store_split2(__nv_bfloat16* oh, __nv_bfloat16* ol,
                                             size_t idx, float v0, float v1) {
    uint32_t lo, hi = pack_bf16_pair(v0, v1, lo);
    *(uint32_t*)(oh + idx) = hi;
    *(uint32_t*)(ol + idx) = lo;
}

// ========== HMMA GEMM body: C = A(MxK)@B^T(NxK); fp32-split bf16 =============
// MODE 0: fp32 C = acc + bias[col]
// MODE 1: KV: v = acc + rs[row&63]*bias[col]; which==0 -> kph/kpl row-major,
//         which==1 -> vth/vtl transposed per-head [bh][d][k]
// MODE 2: Q: v = acc + bias[col]; split -> Oh/Ol row-major
// MODE 3: XEF: v = acc; row>>6 selects xe/xf; scatter [(b,kl)][d] splits
#define STAGES      3
#define STAGE_BYTES 65536
#define GEMM_SMEM   (STAGES * STAGE_BYTES)

template <int MODE>
__device__ __forceinline__ void gemm_body(
    const __nv_bfloat16* __restrict__ Ah, const __nv_bfloat16* __restrict__ Al,
    const __nv_bfloat16* __restrict__ Bh, const __nv_bfloat16* __restrict__ Bl,
    const float* __restrict__ bias, const float* __restrict__ rs,
    float* __restrict__ Cf, __nv_bfloat16* __restrict__ Oh,
    __nv_bfloat16* __restrict__ Ol, int N, int K, int bm0, int bn0, int which)
{
    extern __shared__ __align__(1024) char smem[];
    const uint32_t sb  = smem_u32(smem);
    const int tid  = threadIdx.x;
    const int lane = tid & 31;
    const int wid  = tid >> 5;
    const int wm   = wid >> 1;
    const int wn   = wid & 1;
    const int niter = K / 64;

    float acc[2][8][4] = {};

    auto load_stage = [&](int stage, int it) {
        const uint32_t base = sb + stage * STAGE_BYTES;
        const int k0 = it * 64;
        #pragma unroll
        for (int u = 0; u < 16; u++) {
            int idx  = u * 256 + tid;
            int comp = u >> 2;
            int rem  = idx & 1023;
            int r    = rem >> 3;
            int j    = rem & 7;
            const __nv_bfloat16* p =
                comp == 0 ? Ah : comp == 1 ? Al : comp == 2 ? Bh : Bl;
            int rb = (comp < 2) ? bm0 : bn0;
            uint32_t dst = base + comp * 16384 + sw128((uint32_t)(r * 128 + j * 16));
            cp16(dst, p + (size_t)(rb + r) * K + k0 + j * 8);
        }
    };

    load_stage(0, 0);
    asm volatile("cp.async.commit_group;" ::: "memory");
    if (niter > 1) load_stage(1, 1);
    asm volatile("cp.async.commit_group;" ::: "memory");

    for (int it = 0; it < niter; it++) {
        asm volatile("cp.async.wait_group 1;" ::: "memory");
        __syncthreads();

        int nx = it + 2;
        if (nx < niter) load_stage(nx % STAGES, nx);
        asm volatile("cp.async.commit_group;" ::: "memory");

        const uint32_t st  = sb + (it % STAGES) * STAGE_BYTES;
        const uint32_t sAh = st, sAl = st + 16384, sBh = st + 32768, sBl = st + 49152;

        #pragma unroll
        for (int ks = 0; ks < 4; ks++) {
            uint32_t aH[2][4], aL[2][4], bH[4][4], bL[4][4];
            #pragma unroll
            for (int mi = 0; mi < 2; mi++) {
                int row = wm * 32 + mi * 16 + (lane & 15);
                int col = ks * 32 + ((lane & 16) ? 16 : 0);
                uint32_t off = sw128((uint32_t)(row * 128 + col));
                ldsm4(aH[mi], sAh + off);
                ldsm4(aL[mi], sAl + off);
            }
            #pragma unroll
            for (int ntp = 0; ntp < 4; ntp++) {
                int row = wn * 64 + ntp * 16 + (lane & 7) + ((lane & 16) ? 8 : 0);
                int col = ks * 32 + ((lane & 8) ? 16 : 0);
                uint32_t off = sw128((uint32_t)(row * 128 + col));
                ldsm4(bH[ntp], sBh + off);
                ldsm4(bL[ntp], sBl + off);
            }
            #pragma unroll
            for (int mi = 0; mi < 2; mi++) {
                #pragma unroll
                for (int ni = 0; ni < 8; ni++) {
                    uint32_t b0h = bH[ni >> 1][(ni & 1) * 2];
                    uint32_t b1h = bH[ni >> 1][(ni & 1) * 2 + 1];
                    uint32_t b0l = bL[ni >> 1][(ni & 1) * 2];
                    uint32_t b1l = bL[ni >> 1][(ni & 1) * 2 + 1];
                    mma16816(acc[mi][ni], aH[mi], b0h, b1h);
                    mma16816(acc[mi][ni], aH[mi], b0l, b1l);
                    mma16816(acc[mi][ni], aL[mi], b0h, b1h);
                }
            }
        }
    }

    #pragma unroll
    for (int mi = 0; mi < 2; mi++) {
        #pragma unroll
        for (int ni = 0; ni < 8; ni++) {
            int row = bm0 + wm * 32 + mi * 16 + (lane >> 2);
            int col = bn0 + wn * 64 + ni * 8 + (lane & 3) * 2;
            #pragma unroll
            for (int half = 0; half < 2; half++) {
                int r  = row + half * 8;
                float v0 = acc[mi][ni][half * 2 + 0];
                float v1 = acc[mi][ni][half * 2 + 1];
                if (MODE == 0) {
                    float2 o = {v0 + bias[col], v1 + bias[col + 1]};
                    *(float2*)(Cf + (size_t)r * N + col) = o;
                } else if (MODE == 2) {
                    store_split2(Oh, Ol, (size_t)r * N + col,
                                 v0 + bias[col], v1 + bias[col + 1]);
                } else if (MODE == 1) {
                    float s = rs[r & 63];
                    float w0 = v0 + s * bias[col], w1 = v1 + s * bias[col + 1];
                    if (which == 0) {
                        store_split2(Oh, Ol, (size_t)r * N + col, w0, w1);
                    } else {
                        int b2 = r >> 6, kl = r & 63, hh = col >> 6, d = col & 63;
                        size_t i0 = (((size_t)(b2 * 16 + hh) * 64) + d) * 64 + kl;
                        __nv_bfloat16 h0 = __float2bfloat16(w0);
                        __nv_bfloat16 h1 = __float2bfloat16(w1);
                        Oh[i0]      = h0;
                        Ol[i0]      = __float2bfloat16(w0 - __bfloat162float(h0));
                        Oh[i0 + 64] = h1;
                        Ol[i0 + 64] = __float2bfloat16(w1 - __bfloat162float(h1));
                    }
                } else { // MODE 3: xef scatter
                    int wch = r >> 6, kl = r & 63, b2 = col >> 10, d = col & 1023;
                    __nv_bfloat16* oh = wch ? g_xfh : g_xeh;
                    __nv_bfloat16* ol = wch ? g_xfl : g_xel;
                    store_split2(oh, ol, ((size_t)(b2 * 64 + kl)) * 1024 + d, v0, v1);
                }
            }
        }
    }
}

// Fused xef + Q launch: blocks [0,32) do xef (M=128,N=4096,K=4096);
// blocks [32,1056) do Q (i -> bm0 = (i>>3)*128, bn0 = (i&7)*128).
__global__ __launch_bounds__(256) void gemm_qxef(const float* __restrict__ bqkv)
{
    if (blockIdx.x < 32) {
        gemm_body<3>(g_efh, g_efl, g_xth, g_xtl, nullptr, nullptr,
                     nullptr, nullptr, nullptr,
                     MROWS / 4, NSEQ, 0, blockIdx.x * 128, 0);
    } else {
        int i = blockIdx.x - 32;
        gemm_body<2>(g_xh, g_xl, g_wqh, g_wql, bqkv, nullptr, nullptr,
                     g_qh, g_ql, DIMSZ, DIMSZ,
                     (i >> 3) * 128, (i & 7) * 128, 0);
    }
}
__global__ __launch_bounds__(256) void gemm_kv(const float* __restrict__ bqkv)
{
    const int which = blockIdx.z;
    gemm_body<1>(which ? g_xfh : g_xeh, which ? g_xfl : g_xel,
                 g_wqh + (size_t)(which + 1) * DIMSZ * DIMSZ,
                 g_wql + (size_t)(which + 1) * DIMSZ * DIMSZ,
                 bqkv + (which + 1) * DIMSZ, g_sef + which * KLR, nullptr,
                 which ? g_vth : g_kph, which ? g_vtl : g_kpl,
                 DIMSZ, DIMSZ, blockIdx.y * 128, blockIdx.x * 128, which);
}
__global__ __launch_bounds__(256) void gemm_out(
    const float* __restrict__ bias, float* __restrict__ C)
{
    gemm_body<0>(g_aoh, g_aol, g_woh, g_wol, bias, nullptr, C, nullptr,
                 nullptr, DIMSZ, DIMSZ, blockIdx.y * 128, blockIdx.x * 128, 0);
}

// ============== fused prep: all independent, block-range dispatch ============
// blocks: [0,16384) split x | [16384,19456) tr Wqkv | [19456,20480) tr Wout |
// [20480,36864) tr x->xt | [36864,37120) tr E | [37120,37376) tr F |
// [37376,37504) colsum
__device__ __forceinline__ void tr_body(
    const float* __restrict__ W, __nv_bfloat16* __restrict__ th,
    __nv_bfloat16* __restrict__ tl, int K, int N, int n0, int k0)
{
    __shared__ float t[32][33];
    const int tid = threadIdx.x;
    const int tx = tid & 31, ty = tid >> 5;
    #pragma unroll
    for (int i = 0; i < 4; i++)
        t[ty + i * 8][tx] = W[(size_t)(k0 + ty + i * 8) * N + n0 + tx];
    __syncthreads();
    #pragma unroll
    for (int i = 0; i < 4; i++) {
        int n = n0 + ty + i * 8, k = k0 + tx;
        float v = t[tx][ty + i * 8];
        __nv_bfloat16 h = __float2bfloat16(v);
        th[(size_t)n * K + k] = h;
        tl[(size_t)n * K + k] = __float2bfloat16(v - __bfloat162float(h));
    }
}

__global__ __launch_bounds__(256) void prep_all(
    const float* __restrict__ x, const float* __restrict__ E,
    const float* __restrict__ F, const float* __restrict__ Wqkv,
    const float* __restrict__ Wout)
{
    const int blk = blockIdx.x;
    const int tid = threadIdx.x;
    if (blk < 16384) {                       // split x -> xh/xl
        int i = blk * 256 + tid;
        float4 v = ((const float4*)x)[i];
        float f[4] = {v.x, v.y, v.z, v.w};
        ushort4 uh, ul;
        unsigned short* ph = &uh.x;
        unsigned short* pl = &ul.x;
        #pragma unroll
        for (int j = 0; j < 4; j++) {
            __nv_bfloat16 h = __float2bfloat16(f[j]);
            __nv_bfloat16 l = __float2bfloat16(f[j] - __bfloat162float(h));
            ph[j] = __bfloat16_as_ushort(h);
            pl[j] = __bfloat16_as_ushort(l);
        }
        ((ushort4*)g_xh)[i] = uh;
        ((ushort4*)g_xl)[i] = ul;
    } else if (blk < 19456) {                // tr Wqkv
        int i = blk - 16384;
        tr_body(Wqkv, g_wqh, g_wql, DIMSZ, QKVDIM, (i % 96) * 32, (i / 96) * 32);
    } else if (blk < 20480) {                // tr Wout
        int i = blk - 19456;
        tr_body(Wout, g_woh, g_wol, DIMSZ, DIMSZ, (i % 32) * 32, (i / 32) * 32);
    } else if (blk < 36864) {                // tr x -> xth/xtl
        int i = blk - 20480;
        tr_body(x, g_xth, g_xtl, NSEQ, MROWS / 4, (i % 128) * 32, (i / 128) * 32);
    } else if (blk < 37120) {                // tr E
        int i = blk - 36864;
        tr_body(E, g_efh, g_efl, NSEQ, KLR, (i % 2) * 32, (i / 2) * 32);
    } else if (blk < 37376) {                // tr F
        int i = blk - 37120;
        tr_body(F, g_efh + (size_t)KLR * NSEQ, g_efl + (size_t)KLR * NSEQ,
                NSEQ, KLR, (i % 2) * 32, (i / 2) * 32);
    } else {                                 // colsum E/F
        int i = blk - 37376;
        const int which = i >> 6;
        const int k     = i & 63;
        const float* P  = which ? F : E;
        float s = 0.f;
        for (int n = tid; n < NSEQ; n += 256)
            s += P[(size_t)n * KLR + k];
        __shared__ float red[256];
        red[tid] = s;
        __syncthreads();
        #pragma unroll
        for (int off = 128; off > 0; off >>= 1) {
            if (tid < off) red[tid] += red[tid + off];
            __syncthreads();
        }
        if (tid == 0) g_sef[which * KLR + k] = red[0];
    }
}

// =================== MMA attention: S=QKp^T, softmax, O=PV ===================
#define ATTN_SMEM 65536

__global__ __launch_bounds__(256) void attn_mma()
{
    extern __shared__ __align__(1024) char smem[];
    const uint32_t sb = smem_u32(smem);
    const int tid  = threadIdx.x;
    const int lane = tid & 31;
    const int w    = tid >> 5;
    const int bh   = blockIdx.y;
    const int b    = bh >> 4;
    const int h    = bh & 15;
    const int n0   = blockIdx.x * 128;

    #pragma unroll
    for (int u = 0; u < 8; u++) {           // q tiles (hi then lo)
        int idx = u * 256 + tid;
        int part = idx >> 10, rem = idx & 1023, r = rem >> 3, j = rem & 7;
        const __nv_bfloat16* src =
            (part ? g_ql : g_qh) +
            ((size_t)(n0 + r) * BATCH + b) * DIMSZ + h * 64 + j * 8;
        cp16(sb + part * 16384 + sw128((uint32_t)(r * 128 + j * 16)), src);
    }
    #pragma unroll
    for (int u = 0; u < 4; u++) {           // kp tiles
        int idx = u * 256 + tid;
        int part = idx >> 9, rem = idx & 511, r = rem >> 3, j = rem & 7;
        const __nv_bfloat16* src =
            (part ? g_kpl : g_kph) + (size_t)(b * 64 + r) * DIMSZ + h * 64 + j * 8;
        cp16(sb + 32768 + part * 8192 + sw128((uint32_t)(r * 128 + j * 16)), src);
    }
    #pragma unroll
    for (int u = 0; u < 4; u++) {           // vt tiles
        int idx = u * 256 + tid;
        int part = idx >> 9, rem = idx & 511, r = rem >> 3, j = rem & 7;
        const __nv_bfloat16* src =
            (part ? g_vtl : g_vth) + (size_t)bh * 4096 + r * 64 + j * 8;
        cp16(sb + 49152 + part * 8192 + sw128((uint32_t)(r * 128 + j * 16)), src);
    }
    asm volatile("cp.async.commit_group;" ::: "memory");
    asm volatile("cp.async.wait_group 0;" ::: "memory");
    __syncthreads();

    const uint32_t sQh = sb, sQl = sb + 16384;
    const uint32_t sKh = sb + 32768, sKl = sb + 40960;
    const uint32_t sVh = sb + 49152, sVl = sb + 57344;

    float acc[8][4] = {};
    #pragma unroll
    for (int ks = 0; ks < 4; ks++) {
        uint32_t aH[4], aL[4], bH[4][4], bL[4][4];
        {
            int row = w * 16 + (lane & 15);
            int col = ks * 32 + ((lane & 16) ? 16 : 0);
            uint32_t off = sw128((uint32_t)(row * 128 + col));
            ldsm4(aH, sQh + off);
            ldsm4(aL, sQl + off);
        }
        #pragma unroll
        for (int ntp = 0; ntp < 4; ntp++) {
            int row = ntp * 16 + (lane & 7) + ((lane & 16) ? 8 : 0);
            int col = ks * 32 + ((lane & 8) ? 16 : 0);
            uint32_t off = sw128((uint32_t)(row * 128 + col));
            ldsm4(bH[ntp], sKh + off);
            ldsm4(bL[ntp], sKl + off);
        }
        #pragma unroll
        for (int ni = 0; ni < 8; ni++) {
            uint32_t b0h = bH[ni >> 1][(ni & 1) * 2];
            uint32_t b1h = bH[ni >> 1][(ni & 1) * 2 + 1];
            uint32_t b0l = bL[ni >> 1][(ni & 1) * 2];
            uint32_t b1l = bL[ni >> 1][(ni & 1) * 2 + 1];
            mma16816(acc[ni], aH, b0h, b1h);
            mma16816(acc[ni], aH, b0l, b1l);
            mma16816(acc[ni], aL, b0h, b1h);
        }
    }

    const float scale = 0.125f;
    float m1 = -1e30f, m2 = -1e30f;
    #pragma unroll
    for (int ni = 0; ni < 8; ni++) {
        #pragma unroll
        for (int c = 0; c < 4; c++) acc[ni][c] *= scale;
        m1 = fmaxf(m1, fmaxf(acc[ni][0], acc[ni][1]));
        m2 = fmaxf(m2, fmaxf(acc[ni][2], acc[ni][3]));
    }
    #pragma unroll
    for (int o = 1; o <= 2; o <<= 1) {
        m1 = fmaxf(m1, __shfl_xor_sync(0xffffffffu, m1, o));
        m2 = fmaxf(m2, __shfl_xor_sync(0xffffffffu, m2, o));
    }
    float s1 = 0.f, s2 = 0.f;
    #pragma unroll
    for (int ni = 0; ni < 8; ni++) {
        acc[ni][0] = __expf(acc[ni][0] - m1);
        acc[ni][1] = __expf(acc[ni][1] - m1);
        acc[ni][2] = __expf(acc[ni][2] - m2);
        acc[ni][3] = __expf(acc[ni][3] - m2);
        s1 += acc[ni][0] + acc[ni][1];
        s2 += acc[ni][2] + acc[ni][3];
    }
    #pragma unroll
    for (int o = 1; o <= 2; o <<= 1) {
        s1 += __shfl_xor_sync(0xffffffffu, s1, o);
        s2 += __shfl_xor_sync(0xffffffffu, s2, o);
    }
    float i1 = 1.0f / s1, i2 = 1.0f / s2;
    #pragma unroll
    for (int ni = 0; ni < 8; ni++) {
        acc[ni][0] *= i1; acc[ni][1] *= i1;
        acc[ni][2] *= i2; acc[ni][3] *= i2;
    }

    uint32_t pH[4][4], pL[4][4];
    #pragma unroll
    for (int j = 0; j < 4; j++) {
        pH[j][0] = pack_bf16_pair(acc[2*j][0],   acc[2*j][1],   pL[j][0]);
        pH[j][1] = pack_bf16_pair(acc[2*j][2],   acc[2*j][3],   pL[j][1]);
        pH[j][2] = pack_bf16_pair(acc[2*j+1][0], acc[2*j+1][1], pL[j][2]);
        pH[j][3] = pack_bf16_pair(acc[2*j+1][2], acc[2*j+1][3], pL[j][3]);
    }
    float out[8][4] = {};
    #pragma unroll
    for (int ks = 0; ks < 4; ks++) {
        uint32_t bH[4][4], bL[4][4];
        #pragma unroll
        for (int ntp = 0; ntp < 4; ntp++) {
            int row = ntp * 16 + (lane & 7) + ((lane & 16) ? 8 : 0);
            int col = ks * 32 + ((lane & 8) ? 16 : 0);
            uint32_t off = sw128((uint32_t)(row * 128 + col));
            ldsm4(bH[ntp], sVh + off);
            ldsm4(bL[ntp], sVl + off);
        }
        #pragma unroll
        for (int ni = 0; ni < 8; ni++) {
            uint32_t b0h = bH[ni >> 1][(ni & 1) * 2];
            uint32_t b1h = bH[ni >> 1][(ni & 1) * 2 + 1];
            uint32_t b0l = bL[ni >> 1][(ni & 1) * 2];
            uint32_t b1l = bL[ni >> 1][(ni & 1) * 2 + 1];
            mma16816(out[ni], pH[ks], b0h, b1h);
            mma16816(out[ni], pH[ks], b0l, b1l);
            mma16816(out[ni], pL[ks], b0h, b1h);
        }
    }

    #pragma unroll
    for (int ni = 0; ni < 8; ni++) {
        int r1 = n0 + w * 16 + (lane >> 2);
        int d  = ni * 8 + (lane & 3) * 2;
        size_t i1x = ((size_t)r1 * BATCH + b) * DIMSZ + h * 64 + d;
        store_split2(g_aoh, g_aol, i1x, out[ni][0], out[ni][1]);
        size_t i2x = ((size_t)(r1 + 8) * BATCH + b) * DIMSZ + h * 64 + d;
        store_split2(g_aoh, g_aol, i2x, out[ni][2], out[ni][3]);
    }
}

// ---------------- launch -----------------------------------------------------
extern "C" void kernel_launch(void* const* d_in, const int* in_sizes, int n_in,
                              void* d_out, int out_size)
{
    const float* x    = (const float*)d_in[0];
    const float* E    = (const float*)d_in[1];
    const float* F    = (const float*)d_in[2];
    const float* Wqkv = (const float*)d_in[3];
    const float* bqkv = (const float*)d_in[4];
    const float* Wout = (const float*)d_in[5];
    const float* bout = (const float*)d_in[6];
    float*       out  = (float*)d_out;

    cudaFuncSetAttribute(gemm_qxef, cudaFuncAttributeMaxDynamicSharedMemorySize,
                         GEMM_SMEM);
    cudaFuncSetAttribute(gemm_kv, cudaFuncAttributeMaxDynamicSharedMemorySize,
                         GEMM_SMEM);
    cudaFuncSetAttribute(gemm_out, cudaFuncAttributeMaxDynamicSharedMemorySize,
                         GEMM_SMEM);
    cudaFuncSetAttribute(attn_mma, cudaFuncAttributeMaxDynamicSharedMemorySize,
                         ATTN_SMEM);

    // 0) prep: one fused launch (all parts independent, read only inputs)
    prep_all<<<37504, 256>>>(x, E, F, Wqkv, Wout);

    // 1+2) fused: xef (32 blocks) + Q (1024 blocks)   [HMMA]
    gemm_qxef<<<1056, 256, GEMM_SMEM>>>(bqkv);

    // 3) Kp/Vp (+ colsum*bias) -> kp / vt splits   [HMMA]
    gemm_kv<<<dim3(8, 2, 2), 256, GEMM_SMEM>>>(bqkv);

    // 4) attention  [HMMA]
    attn_mma<<<dim3(NSEQ / 128, BATCH * NHEAD), 256, ATTN_SMEM>>>();

    // 5) out = ao @ Wout + bout   [HMMA, fp32 C]
    gemm_out<<<dim3(DIMSZ / 128, MROWS / 128), 256, GEMM_SMEM>>>(bout, out);
}

// round 17
// speedup vs baseline: 1.6254x; 1.0580x over previous
#include <cuda_runtime.h>
#include <cuda_bf16.h>
#include <cstdint>
#include <cstddef>

#define NSEQ   4096
#define BATCH  4
#define DIMSZ  1024
#define NHEAD  16
#define KLR    64
#define DH     64
#define MROWS  (NSEQ*BATCH)     /* 16384 */
#define QKVDIM (3*DIMSZ)        /* 3072  */

// ---------------- scratch (static device globals; no allocation) -------------
__device__ float g_sef[2 * KLR];                           // col sums of E, F
__device__ int   g_xef_done;                               // xef completion ctr
__device__ __nv_bfloat16 g_xh [(size_t)MROWS * DIMSZ];     // x split [n][(b,d)]
__device__ __nv_bfloat16 g_xl [(size_t)MROWS * DIMSZ];
__device__ __nv_bfloat16 g_xth[(size_t)MROWS * DIMSZ];     // x^T [(b,d)][n]
__device__ __nv_bfloat16 g_xtl[(size_t)MROWS * DIMSZ];
__device__ __nv_bfloat16 g_efh[128 * NSEQ];                // [E^T;F^T] stacked
__device__ __nv_bfloat16 g_efl[128 * NSEQ];
__device__ __nv_bfloat16 g_xeh[(size_t)BATCH * KLR * DIMSZ];
__device__ __nv_bfloat16 g_xel[(size_t)BATCH * KLR * DIMSZ];
__device__ __nv_bfloat16 g_xfh[(size_t)BATCH * KLR * DIMSZ];
__device__ __nv_bfloat16 g_xfl[(size_t)BATCH * KLR * DIMSZ];
__device__ __nv_bfloat16 g_wqh[(size_t)QKVDIM * DIMSZ];    // W_qkv^T split
__device__ __nv_bfloat16 g_wql[(size_t)QKVDIM * DIMSZ];
__device__ __nv_bfloat16 g_woh[(size_t)DIMSZ * DIMSZ];     // W_out^T split
__device__ __nv_bfloat16 g_wol[(size_t)DIMSZ * DIMSZ];
__device__ __nv_bfloat16 g_qh [(size_t)MROWS * DIMSZ];     // Q split [(n,b)][d]
__device__ __nv_bfloat16 g_ql [(size_t)MROWS * DIMSZ];
__device__ __nv_bfloat16 g_kph[(size_t)BATCH * KLR * DIMSZ]; // Kp [b*64+kl][h*64+d]
__device__ __nv_bfloat16 g_kpl[(size_t)BATCH * KLR * DIMSZ];
__device__ __nv_bfloat16 g_vth[(size_t)BATCH * NHEAD * DH * KLR]; // V^T [bh][d][k]
__device__ __nv_bfloat16 g_vtl[(size_t)BATCH * NHEAD * DH * KLR];
__device__ __nv_bfloat16 g_aoh[(size_t)MROWS * DIMSZ];     // attn out split
__device__ __nv_bfloat16 g_aol[(size_t)MROWS * DIMSZ];

// ============================ small helpers ==================================
__device__ __forceinline__ uint32_t smem_u32(const void* p) {
    uint32_t a;
    asm("{ .reg .u64 t; cvta.to.shared.u64 t, %1; cvt.u32.u64 %0, t; }"
        : "=r"(a) : "l"(p));
    return a;
}
__device__ __forceinline__ uint32_t sw128(uint32_t off) {
    return off ^ ((off >> 3) & 0x70);
}
__device__ __forceinline__ void cp16(uint32_t dst, const void* src) {
    asm volatile("cp.async.cg.shared.global [%0], [%1], 16;"
                 :: "r"(dst), "l"(src));
}
__device__ __forceinline__ void ldsm4(uint32_t* r, uint32_t addr) {
    asm volatile("ldmatrix.sync.aligned.m8n8.x4.shared.b16 {%0,%1,%2,%3}, [%4];"
                 : "=r"(r[0]), "=r"(r[1]), "=r"(r[2]), "=r"(r[3]) : "r"(addr));
}
__device__ __forceinline__ void mma16816(float* c, const uint32_t* a,
                                         uint32_t b0, uint32_t b1) {
    asm volatile(
        "mma.sync.aligned.m16n8k16.row.col.f32.bf16.bf16.f32 "
        "{%0,%1,%2,%3}, {%4,%5,%6,%7}, {%8,%9}, {%0,%1,%2,%3};"
        : "+f"(c[0]), "+f"(c[1]), "+f"(c[2]), "+f"(c[3])
        : "r"(a[0]), "r"(a[1]), "r"(a[2]), "r"(a[3]), "r"(b0), "r"(b1));
}
__device__ __forceinline__ uint32_t pack_bf16_pair(float x, float y,
                                                   uint32_t& lo_out) {
    __nv_bfloat16 hx = __float2bfloat16(x);
    __nv_bfloat16 hy = __float2bfloat16(y);
    __nv_bfloat16 lx = __float2bfloat16(x - __bfloat162float(hx));
    __nv_bfloat16 ly = __float2bfloat16(y - __bfloat162float(hy));
    lo_out = (uint32_t)__bfloat16_as_ushort(lx) |
             ((uint32_t)__bfloat16_as_ushort(ly) << 16);
    return (uint32_t)__bfloat16_as_ushort(hx) |
           ((uint32_t)__bfloat16_as_ushort(hy) << 16);
}
__device__ __forceinline__ void store_split2(__nv_bfloat16* oh, __nv_bfloat16* ol,
                                             size_t idx, float v0, float v1) {
    uint32_t lo, hi = pack_bf16_pair(v0, v1, lo);
    *(uint32_t*)(oh + idx) = hi;
    *(uint32_t*)(ol + idx) = lo;
}

// ========== HMMA GEMM body: C = A(MxK)@B^T(NxK); fp32-split bf16 =============
// MODE 0: fp32 C = acc + bias[col]
// MODE 1: KV: v = acc + rs[row&63]*bias[col]; which==0 -> kph/kpl row-major,
//         which==1 -> vth/vtl transposed per-head [bh][d][k]
// MODE 2: Q: v = acc + bias[col]; split -> Oh/Ol row-major
// MODE 3: XEF: v = acc; row>>6 selects xe/xf; scatter [(b,kl)][d] splits
#define STAGES      3
#define STAGE_BYTES 65536
#define GEMM_SMEM   (STAGES * STAGE_BYTES)

template <int MODE>
__device__ __forceinline__ void gemm_body(
    const __nv_bfloat16* __restrict__ Ah, const __nv_bfloat16* __restrict__ Al,
    const __nv_bfloat16* __restrict__ Bh, const __nv_bfloat16* __restrict__ Bl,
    const float* __restrict__ bias, const float* __restrict__ rs,
    float* __restrict__ Cf, __nv_bfloat16* __restrict__ Oh,
    __nv_bfloat16* __restrict__ Ol, int N, int K, int bm0, int bn0, int which)
{
    extern __shared__ __align__(1024) char smem[];
    const uint32_t sb  = smem_u32(smem);
    const int tid  = threadIdx.x;
    const int lane = tid & 31;
    const int wid  = tid >> 5;
    const int wm   = wid >> 1;
    const int wn   = wid & 1;
    const int niter = K / 64;

    float acc[2][8][4] = {};

    auto load_stage = [&](int stage, int it) {
        const uint32_t base = sb + stage * STAGE_BYTES;
        const int k0 = it * 64;
        #pragma unroll
        for (int u = 0; u < 16; u++) {
            int idx  = u * 256 + tid;
            int comp = u >> 2;
            int rem  = idx & 1023;
            int r    = rem >> 3;
            int j    = rem & 7;
            const __nv_bfloat16* p =
                comp == 0 ? Ah : comp == 1 ? Al : comp == 2 ? Bh : Bl;
            int rb = (comp < 2) ? bm0 : bn0;
            uint32_t dst = base + comp * 16384 + sw128((uint32_t)(r * 128 + j * 16));
            cp16(dst, p + (size_t)(rb + r) * K + k0 + j * 8);
        }
    };

    load_stage(0, 0);
    asm volatile("cp.async.commit_group;" ::: "memory");
    if (niter > 1) load_stage(1, 1);
    asm volatile("cp.async.commit_group;" ::: "memory");

    for (int it = 0; it < niter; it++) {
        asm volatile("cp.async.wait_group 1;" ::: "memory");
        __syncthreads();

        int nx = it + 2;
        if (nx < niter) load_stage(nx % STAGES, nx);
        asm volatile("cp.async.commit_group;" ::: "memory");

        const uint32_t st  = sb + (it % STAGES) * STAGE_BYTES;
        const uint32_t sAh = st, sAl = st + 16384, sBh = st + 32768, sBl = st + 49152;

        #pragma unroll
        for (int ks = 0; ks < 4; ks++) {
            uint32_t aH[2][4], aL[2][4], bH[4][4], bL[4][4];
            #pragma unroll
            for (int mi = 0; mi < 2; mi++) {
                int row = wm * 32 + mi * 16 + (lane & 15);
                int col = ks * 32 + ((lane & 16) ? 16 : 0);
                uint32_t off = sw128((uint32_t)(row * 128 + col));
                ldsm4(aH[mi], sAh + off);
                ldsm4(aL[mi], sAl + off);
            }
            #pragma unroll
            for (int ntp = 0; ntp < 4; ntp++) {
                int row = wn * 64 + ntp * 16 + (lane & 7) + ((lane & 16) ? 8 : 0);
                int col = ks * 32 + ((lane & 8) ? 16 : 0);
                uint32_t off = sw128((uint32_t)(row * 128 + col));
                ldsm4(bH[ntp], sBh + off);
                ldsm4(bL[ntp], sBl + off);
            }
            #pragma unroll
            for (int mi = 0; mi < 2; mi++) {
                #pragma unroll
                for (int ni = 0; ni < 8; ni++) {
                    uint32_t b0h = bH[ni >> 1][(ni & 1) * 2];
                    uint32_t b1h = bH[ni >> 1][(ni & 1) * 2 + 1];
                    uint32_t b0l = bL[ni >> 1][(ni & 1) * 2];
                    uint32_t b1l = bL[ni >> 1][(ni & 1) * 2 + 1];
                    mma16816(acc[mi][ni], aH[mi], b0h, b1h);
                    mma16816(acc[mi][ni], aH[mi], b0l, b1l);
                    mma16816(acc[mi][ni], aL[mi], b0h, b1h);
                }
            }
        }
    }

    #pragma unroll
    for (int mi = 0; mi < 2; mi++) {
        #pragma unroll
        for (int ni = 0; ni < 8; ni++) {
            int row = bm0 + wm * 32 + mi * 16 + (lane >> 2);
            int col = bn0 + wn * 64 + ni * 8 + (lane & 3) * 2;
            #pragma unroll
            for (int half = 0; half < 2; half++) {
                int r  = row + half * 8;
                float v0 = acc[mi][ni][half * 2 + 0];
                float v1 = acc[mi][ni][half * 2 + 1];
                if (MODE == 0) {
                    float2 o = {v0 + bias[col], v1 + bias[col + 1]};
                    *(float2*)(Cf + (size_t)r * N + col) = o;
                } else if (MODE == 2) {
                    store_split2(Oh, Ol, (size_t)r * N + col,
                                 v0 + bias[col], v1 + bias[col + 1]);
                } else if (MODE == 1) {
                    float s = rs[r & 63];
                    float w0 = v0 + s * bias[col], w1 = v1 + s * bias[col + 1];
                    if (which == 0) {
                        store_split2(Oh, Ol, (size_t)r * N + col, w0, w1);
                    } else {
                        int b2 = r >> 6, kl = r & 63, hh = col >> 6, d = col & 63;
                        size_t i0 = (((size_t)(b2 * 16 + hh) * 64) + d) * 64 + kl;
                        __nv_bfloat16 h0 = __float2bfloat16(w0);
                        __nv_bfloat16 h1 = __float2bfloat16(w1);
                        Oh[i0]      = h0;
                        Ol[i0]      = __float2bfloat16(w0 - __bfloat162float(h0));
                        Oh[i0 + 64] = h1;
                        Ol[i0 + 64] = __float2bfloat16(w1 - __bfloat162float(h1));
                    }
                } else { // MODE 3: xef scatter
                    int wch = r >> 6, kl = r & 63, b2 = col >> 10, d = col & 1023;
                    __nv_bfloat16* oh = wch ? g_xfh : g_xeh;
                    __nv_bfloat16* ol = wch ? g_xfl : g_xel;
                    store_split2(oh, ol, ((size_t)(b2 * 64 + kl)) * 1024 + d, v0, v1);
                }
            }
        }
    }
}

// Fused xef + Q + KV launch:
//   blocks [0,32)      : xef (M=128,N=4096,K=4096); signals g_xef_done
//   blocks [32,1056)   : Q   (i -> bm0=(i>>3)*128, bn0=(i&7)*128)
//   blocks [1056,1088) : KV  (spin on g_xef_done==32; deadlock-free: xef
//                        blocks have lowest indices -> dispatched first)
__global__ __launch_bounds__(256) void gemm_qxefkv(const float* __restrict__ bqkv)
{
    if (blockIdx.x < 32) {
        gemm_body<3>(g_efh, g_efl, g_xth, g_xtl, nullptr, nullptr,
                     nullptr, nullptr, nullptr,
                     MROWS / 4, NSEQ, 0, blockIdx.x * 128, 0);
        __threadfence();
        __syncthreads();
        if (threadIdx.x == 0) atomicAdd(&g_xef_done, 1);
    } else if (blockIdx.x < 1056) {
        int i = blockIdx.x - 32;
        gemm_body<2>(g_xh, g_xl, g_wqh, g_wql, bqkv, nullptr, nullptr,
                     g_qh, g_ql, DIMSZ, DIMSZ,
                     (i >> 3) * 128, (i & 7) * 128, 0);
    } else {
        if (threadIdx.x == 0) {
            while (atomicAdd(&g_xef_done, 0) < 32) { }
        }
        __syncthreads();
        int i = blockIdx.x - 1056;
        const int which = i >> 4;
        const int rem   = i & 15;
        gemm_body<1>(which ? g_xfh : g_xeh, which ? g_xfl : g_xel,
                     g_wqh + (size_t)(which + 1) * DIMSZ * DIMSZ,
                     g_wql + (size_t)(which + 1) * DIMSZ * DIMSZ,
                     bqkv + (which + 1) * DIMSZ, g_sef + which * KLR, nullptr,
                     which ? g_vth : g_kph, which ? g_vtl : g_kpl,
                     DIMSZ, DIMSZ, (rem >> 3) * 128, (rem & 7) * 128, which);
    }
}
__global__ __launch_bounds__(256) void gemm_out(
    const float* __restrict__ bias, float* __restrict__ C)
{
    gemm_body<0>(g_aoh, g_aol, g_woh, g_wol, bias, nullptr, C, nullptr,
                 nullptr, DIMSZ, DIMSZ, blockIdx.y * 128, blockIdx.x * 128, 0);
}

// ============== fused prep: all independent, block-range dispatch ============
// blocks: [0,16384) split x | [16384,19456) tr Wqkv | [19456,20480) tr Wout |
// [20480,36864) tr x->xt | [36864,37120) tr E | [37120,37376) tr F |
// [37376,37504) colsum   (block 0 also resets g_xef_done)
__device__ __forceinline__ void tr_body(
    const float* __restrict__ W, __nv_bfloat16* __restrict__ th,
    __nv_bfloat16* __restrict__ tl, int K, int N, int n0, int k0)
{
    __shared__ float t[32][33];
    const int tid = threadIdx.x;
    const int tx = tid & 31, ty = tid >> 5;
    #pragma unroll
    for (int i = 0; i < 4; i++)
        t[ty + i * 8][tx] = W[(size_t)(k0 + ty + i * 8) * N + n0 + tx];
    __syncthreads();
    #pragma unroll
    for (int i = 0; i < 4; i++) {
        int n = n0 + ty + i * 8, k = k0 + tx;
        float v = t[tx][ty + i * 8];
        __nv_bfloat16 h = __float2bfloat16(v);
        th[(size_t)n * K + k] = h;
        tl[(size_t)n * K + k] = __float2bfloat16(v - __bfloat162float(h));
    }
}

__global__ __launch_bounds__(256) void prep_all(
    const float* __restrict__ x, const float* __restrict__ E,
    const float* __restrict__ F, const float* __restrict__ Wqkv,
    const float* __restrict__ Wout)
{
    const int blk = blockIdx.x;
    const int tid = threadIdx.x;
    if (blk == 0 && tid == 0) g_xef_done = 0;
    if (blk < 16384) {                       // split x -> xh/xl
        int i = blk * 256 + tid;
        float4 v = ((const float4*)x)[i];
        float f[4] = {v.x, v.y, v.z, v.w};
        ushort4 uh, ul;
        unsigned short* ph = &uh.x;
        unsigned short* pl = &ul.x;
        #pragma unroll
        for (int j = 0; j < 4; j++) {
            __nv_bfloat16 h = __float2bfloat16(f[j]);
            __nv_bfloat16 l = __float2bfloat16(f[j] - __bfloat162float(h));
            ph[j] = __bfloat16_as_ushort(h);
            pl[j] = __bfloat16_as_ushort(l);
        }
        ((ushort4*)g_xh)[i] = uh;
        ((ushort4*)g_xl)[i] = ul;
    } else if (blk < 19456) {                // tr Wqkv
        int i = blk - 16384;
        tr_body(Wqkv, g_wqh, g_wql, DIMSZ, QKVDIM, (i % 96) * 32, (i / 96) * 32);
    } else if (blk < 20480) {                // tr Wout
        int i = blk - 19456;
        tr_body(Wout, g_woh, g_wol, DIMSZ, DIMSZ, (i % 32) * 32, (i / 32) * 32);
    } else if (blk < 36864) {                // tr x -> xth/xtl
        int i = blk - 20480;
        tr_body(x, g_xth, g_xtl, NSEQ, MROWS / 4, (i % 128) * 32, (i / 128) * 32);
    } else if (blk < 37120) {                // tr E
        int i = blk - 36864;
        tr_body(E, g_efh, g_efl, NSEQ, KLR, (i % 2) * 32, (i / 2) * 32);
    } else if (blk < 37376) {                // tr F
        int i = blk - 37120;
        tr_body(F, g_efh + (size_t)KLR * NSEQ, g_efl + (size_t)KLR * NSEQ,
                NSEQ, KLR, (i % 2) * 32, (i / 2) * 32);
    } else {                                 // colsum E/F
        int i = blk - 37376;
        const int which = i >> 6;
        const int k     = i & 63;
        const float* P  = which ? F : E;
        float s = 0.f;
        for (int n = tid; n < NSEQ; n += 256)
            s += P[(size_t)n * KLR + k];
        __shared__ float red[256];
        red[tid] = s;
        __syncthreads();
        #pragma unroll
        for (int off = 128; off > 0; off >>= 1) {
            if (tid < off) red[tid] += red[tid + off];
            __syncthreads();
        }
        if (tid == 0) g_sef[which * KLR + k] = red[0];
    }
}

// =================== MMA attention: S=QKp^T, softmax, O=PV ===================
#define ATTN_SMEM 65536

__global__ __launch_bounds__(256) void attn_mma()
{
    extern __shared__ __align__(1024) char smem[];
    const uint32_t sb = smem_u32(smem);
    const int tid  = threadIdx.x;
    const int lane = tid & 31;
    const int w    = tid >> 5;
    const int bh   = blockIdx.y;
    const int b    = bh >> 4;
    const int h    = bh & 15;
    const int n0   = blockIdx.x * 128;

    #pragma unroll
    for (int u = 0; u < 8; u++) {           // q tiles (hi then lo)
        int idx = u * 256 + tid;
        int part = idx >> 10, rem = idx & 1023, r = rem >> 3, j = rem & 7;
        const __nv_bfloat16* src =
            (part ? g_ql : g_qh) +
            ((size_t)(n0 + r) * BATCH + b) * DIMSZ + h * 64 + j * 8;
        cp16(sb + part * 16384 + sw128((uint32_t)(r * 128 + j * 16)), src);
    }
    #pragma unroll
    for (int u = 0; u < 4; u++) {           // kp tiles
        int idx = u * 256 + tid;
        int part = idx >> 9, rem = idx & 511, r = rem >> 3, j = rem & 7;
        const __nv_bfloat16* src =
            (part ? g_kpl : g_kph) + (size_t)(b * 64 + r) * DIMSZ + h * 64 + j * 8;
        cp16(sb + 32768 + part * 8192 + sw128((uint32_t)(r * 128 + j * 16)), src);
    }
    #pragma unroll
    for (int u = 0; u < 4; u++) {           // vt tiles
        int idx = u * 256 + tid;
        int part = idx >> 9, rem = idx & 511, r = rem >> 3, j = rem & 7;
        const __nv_bfloat16* src =
            (part ? g_vtl : g_vth) + (size_t)bh * 4096 + r * 64 + j * 8;
        cp16(sb + 49152 + part * 8192 + sw128((uint32_t)(r * 128 + j * 16)), src);
    }
    asm volatile("cp.async.commit_group;" ::: "memory");
    asm volatile("cp.async.wait_group 0;" ::: "memory");
    __syncthreads();

    const uint32_t sQh = sb, sQl = sb + 16384;
    const uint32_t sKh = sb + 32768, sKl = sb + 40960;
    const uint32_t sVh = sb + 49152, sVl = sb + 57344;

    float acc[8][4] = {};
    #pragma unroll
    for (int ks = 0; ks < 4; ks++) {
        uint32_t aH[4], aL[4], bH[4][4], bL[4][4];
        {
            int row = w * 16 + (lane & 15);
            int col = ks * 32 + ((lane & 16) ? 16 : 0);
            uint32_t off = sw128((uint32_t)(row * 128 + col));
            ldsm4(aH, sQh + off);
            ldsm4(aL, sQl + off);
        }
        #pragma unroll
        for (int ntp = 0; ntp < 4; ntp++) {
            int row = ntp * 16 + (lane & 7) + ((lane & 16) ? 8 : 0);
            int col = ks * 32 + ((lane & 8) ? 16 : 0);
            uint32_t off = sw128((uint32_t)(row * 128 + col));
            ldsm4(bH[ntp], sKh + off);
            ldsm4(bL[ntp], sKl + off);
        }
        #pragma unroll
        for (int ni = 0; ni < 8; ni++) {
            uint32_t b0h = bH[ni >> 1][(ni & 1) * 2];
            uint32_t b1h = bH[ni >> 1][(ni & 1) * 2 + 1];
            uint32_t b0l = bL[ni >> 1][(ni & 1) * 2];
            uint32_t b1l = bL[ni >> 1][(ni & 1) * 2 + 1];
            mma16816(acc[ni], aH, b0h, b1h);
            mma16816(acc[ni], aH, b0l, b1l);
            mma16816(acc[ni], aL, b0h, b1h);
        }
    }

    const float scale = 0.125f;
    float m1 = -1e30f, m2 = -1e30f;
    #pragma unroll
    for (int ni = 0; ni < 8; ni++) {
        #pragma unroll
        for (int c = 0; c < 4; c++) acc[ni][c] *= scale;
        m1 = fmaxf(m1, fmaxf(acc[ni][0], acc[ni][1]));
        m2 = fmaxf(m2, fmaxf(acc[ni][2], acc[ni][3]));
    }
    #pragma unroll
    for (int o = 1; o <= 2; o <<= 1) {
        m1 = fmaxf(m1, __shfl_xor_sync(0xffffffffu, m1, o));
        m2 = fmaxf(m2, __shfl_xor_sync(0xffffffffu, m2, o));
    }
    float s1 = 0.f, s2 = 0.f;
    #pragma unroll
    for (int ni = 0; ni < 8; ni++) {
        acc[ni][0] = __expf(acc[ni][0] - m1);
        acc[ni][1] = __expf(acc[ni][1] - m1);
        acc[ni][2] = __expf(acc[ni][2] - m2);
        acc[ni][3] = __expf(acc[ni][3] - m2);
        s1 += acc[ni][0] + acc[ni][1];
        s2 += acc[ni][2] + acc[ni][3];
    }
    #pragma unroll
    for (int o = 1; o <= 2; o <<= 1) {
        s1 += __shfl_xor_sync(0xffffffffu, s1, o);
        s2 += __shfl_xor_sync(0xffffffffu, s2, o);
    }
    float i1 = 1.0f / s1, i2 = 1.0f / s2;
    #pragma unroll
    for (int ni = 0; ni < 8; ni++) {
        acc[ni][0] *= i1; acc[ni][1] *= i1;
        acc[ni][2] *= i2; acc[ni][3] *= i2;
    }

    uint32_t pH[4][4], pL[4][4];
    #pragma unroll
    for (int j = 0; j < 4; j++) {
        pH[j][0] = pack_bf16_pair(acc[2*j][0],   acc[2*j][1],   pL[j][0]);
        pH[j][1] = pack_bf16_pair(acc[2*j][2],   acc[2*j][3],   pL[j][1]);
        pH[j][2] = pack_bf16_pair(acc[2*j+1][0], acc[2*j+1][1], pL[j][2]);
        pH[j][3] = pack_bf16_pair(acc[2*j+1][2], acc[2*j+1][3], pL[j][3]);
    }
    float out[8][4] = {};
    #pragma unroll
    for (int ks = 0; ks < 4; ks++) {
        uint32_t bH[4][4], bL[4][4];
        #pragma unroll
        for (int ntp = 0; ntp < 4; ntp++) {
            int row = ntp * 16 + (lane & 7) + ((lane & 16) ? 8 : 0);
            int col = ks * 32 + ((lane & 8) ? 16 : 0);
            uint32_t off = sw128((uint32_t)(row * 128 + col));
            ldsm4(bH[ntp], sVh + off);
            ldsm4(bL[ntp], sVl + off);
        }
        #pragma unroll
        for (int ni = 0; ni < 8; ni++) {
            uint32_t b0h = bH[ni >> 1][(ni & 1) * 2];
            uint32_t b1h = bH[ni >> 1][(ni & 1) * 2 + 1];
            uint32_t b0l = bL[ni >> 1][(ni & 1) * 2];
            uint32_t b1l = bL[ni >> 1][(ni & 1) * 2 + 1];
            mma16816(out[ni], pH[ks], b0h, b1h);
            mma16816(out[ni], pH[ks], b0l, b1l);
            mma16816(out[ni], pL[ks], b0h, b1h);
        }
    }

    #pragma unroll
    for (int ni = 0; ni < 8; ni++) {
        int r1 = n0 + w * 16 + (lane >> 2);
        int d  = ni * 8 + (lane & 3) * 2;
        size_t i1x = ((size_t)r1 * BATCH + b) * DIMSZ + h * 64 + d;
        store_split2(g_aoh, g_aol, i1x, out[ni][0], out[ni][1]);
        size_t i2x = ((size_t)(r1 + 8) * BATCH + b) * DIMSZ + h * 64 + d;
        store_split2(g_aoh, g_aol, i2x, out[ni][2], out[ni][3]);
    }
}

// ---------------- launch -----------------------------------------------------
extern "C" void kernel_launch(void* const* d_in, const int* in_sizes, int n_in,
                              void* d_out, int out_size)
{
    const float* x    = (const float*)d_in[0];
    const float* E    = (const float*)d_in[1];
    const float* F    = (const float*)d_in[2];
    const float* Wqkv = (const float*)d_in[3];
    const float* bqkv = (const float*)d_in[4];
    const float* Wout = (const float*)d_in[5];
    const float* bout = (const float*)d_in[6];
    float*       out  = (float*)d_out;

    cudaFuncSetAttribute(gemm_qxefkv,
                         cudaFuncAttributeMaxDynamicSharedMemorySize, GEMM_SMEM);
    cudaFuncSetAttribute(gemm_out, cudaFuncAttributeMaxDynamicSharedMemorySize,
                         GEMM_SMEM);
    cudaFuncSetAttribute(attn_mma, cudaFuncAttributeMaxDynamicSharedMemorySize,
                         ATTN_SMEM);

    // 0) prep: one fused launch (also resets the xef-done counter)
    prep_all<<<37504, 256>>>(x, E, F, Wqkv, Wout);

    // 1+2+3) fused: xef (32) + Q (1024) + KV (32, guarded)   [HMMA]
    gemm_qxefkv<<<1088, 256, GEMM_SMEM>>>(bqkv);

    // 4) attention  [HMMA]
    attn_mma<<<dim3(NSEQ / 128, BATCH * NHEAD), 256, ATTN_SMEM>>>();

    // 5) out = ao @ Wout + bout   [HMMA, fp32 C]
    gemm_out<<<dim3(DIMSZ / 128, MROWS / 128), 256, GEMM_SMEM>>>(bout, out);
}